// round 13
// baseline (speedup 1.0000x reference)
#include <cuda_runtime.h>
#include <cuda_fp16.h>
#include <cstdint>
#include <cstddef>

#define DD 128
#define VMAX 100000
#define EMAX 524288

// ---------------------------------------------------------------------------
// Global scratch (no allocs allowed)
// ---------------------------------------------------------------------------
__device__ float g_Y[2u * VMAX * DD];             // Y_in | Y_out, fp32
__device__ float g_stats[2 * DD];                 // BN sum / sumsq
__device__ __align__(16) unsigned char g_Bh[6 * 16384];  // W fp16 image
__device__ int g_deg[2 * VMAX];                   // per (dir,node) degree
__device__ int g_off[2 * VMAX + 1];               // CSR offsets
__device__ int g_cur[2 * VMAX];                   // fill cursors
__device__ int g_eid[EMAX];                       // dst-sorted edge ids
__device__ int g_bsum[256];                       // scan block sums

// ---------------------------------------------------------------------------
// PTX helpers (generic-target safe: ldmatrix + mma.sync + cp.async)
// ---------------------------------------------------------------------------
__device__ __forceinline__ uint32_t smem_u32(const void* p) {
    uint32_t a;
    asm("{ .reg .u64 t; cvta.to.shared.u64 t, %1; cvt.u32.u64 %0, t; }" : "=r"(a) : "l"(p));
    return a;
}

#define LDSM4(r, addr)                                                          \
    asm volatile("ldmatrix.sync.aligned.m8n8.x4.shared.b16 {%0,%1,%2,%3}, [%4];" \
        : "=r"((r)[0]), "=r"((r)[1]), "=r"((r)[2]), "=r"((r)[3]) : "r"(addr))

#define MMA16816F16(d, a, b0, b1)                                               \
    asm volatile("mma.sync.aligned.m16n8k16.row.col.f32.f16.f16.f32 "           \
        "{%0,%1,%2,%3}, {%4,%5,%6,%7}, {%8,%9}, {%0,%1,%2,%3};"                 \
        : "+f"((d)[0]), "+f"((d)[1]), "+f"((d)[2]), "+f"((d)[3])                \
        : "r"((a)[0]), "r"((a)[1]), "r"((a)[2]), "r"((a)[3]), "r"(b0), "r"(b1))

#define CP_ASYNC16(saddr, gptr)                                                 \
    asm volatile("cp.async.cg.shared.global [%0], [%1], 16;"                    \
        :: "r"(saddr), "l"(gptr) : "memory")
#define CP_COMMIT()  asm volatile("cp.async.commit_group;" ::: "memory")
#define CP_WAIT0()   asm volatile("cp.async.wait_group 0;" ::: "memory")

// fp16 split: hi = rn(z), lo = rn(z - hi).
__device__ __forceinline__ void split4h(const float4 z, uint2& hi, uint2& lo) {
    __half2 h01 = __floats2half2_rn(z.x, z.y);
    __half2 h23 = __floats2half2_rn(z.z, z.w);
    float2 f01 = __half22float2(h01);
    float2 f23 = __half22float2(h23);
    __half2 l01 = __floats2half2_rn(z.x - f01.x, z.y - f01.y);
    __half2 l23 = __floats2half2_rn(z.z - f23.x, z.w - f23.y);
    hi.x = *reinterpret_cast<uint32_t*>(&h01);
    hi.y = *reinterpret_cast<uint32_t*>(&h23);
    lo.x = *reinterpret_cast<uint32_t*>(&l01);
    lo.y = *reinterpret_cast<uint32_t*>(&l23);
}

// ---------------------------------------------------------------------------
// Kernel 0: W image, fp16, 6 chunks of [128 n][64 k]. loop_rel folded in.
// ---------------------------------------------------------------------------
__global__ void prep_w(const float* __restrict__ in_w, const float* __restrict__ out_w,
                       const float* __restrict__ loop_w,
                       const float* __restrict__ loop_rel) {
    int c = blockIdx.x;
    const float* W = (c < 2) ? in_w : (c < 4 ? out_w : loop_w);
    int k0 = (c & 1) * 64;
    __half* bh = reinterpret_cast<__half*>(g_Bh + c * 16384);
    for (int i = threadIdx.x; i < 8192; i += blockDim.x) {
        int n = i >> 6, k = i & 63;
        float v = W[(size_t)(k0 + k) * DD + n];
        if (c >= 4) v *= loop_rel[k0 + k];
        bh[n * 64 + k] = __float2half_rn(v);
    }
}

// ---------------------------------------------------------------------------
// CSR build: histogram -> 3-kernel exclusive scan -> fill
// node id = (e < half ? 0 : V) + dst[e],  N = 2V entries.
// ---------------------------------------------------------------------------
__global__ void hist_kernel(const int* __restrict__ dst, int E, int half, int V) {
    int e = blockIdx.x * blockDim.x + threadIdx.x;
    if (e >= E) return;
    int node = (e < half ? 0 : V) + __ldg(&dst[e]);
    atomicAdd(&g_deg[node], 1);
}

// scan1: per-1024-block sums of g_deg
__global__ void scan1_kernel(int N) {
    __shared__ int sh[256];
    int b = blockIdx.x, t = threadIdx.x;
    int base = b * 1024 + t * 4;
    int s = 0;
#pragma unroll
    for (int j = 0; j < 4; j++) {
        int idx = base + j;
        if (idx < N) s += g_deg[idx];
    }
    sh[t] = s;
    __syncthreads();
    for (int off = 128; off > 0; off >>= 1) {
        if (t < off) sh[t] += sh[t + off];
        __syncthreads();
    }
    if (t == 0) g_bsum[b] = sh[0];
}

// scan2: serial exclusive scan of block sums; writes g_off[N] = total
__global__ void scan2_kernel(int NB, int N) {
    if (threadIdx.x == 0) {
        int acc = 0;
        for (int i = 0; i < NB; i++) {
            int v = g_bsum[i];
            g_bsum[i] = acc;
            acc += v;
        }
        g_off[N] = acc;
    }
}

// scan3: per-block exclusive scan + block offset; writes g_off and g_cur
__global__ void scan3_kernel(int N) {
    __shared__ int sh[256];
    int b = blockIdx.x, t = threadIdx.x;
    int base = b * 1024 + t * 4;
    int v[4];
    int s = 0;
#pragma unroll
    for (int j = 0; j < 4; j++) {
        int idx = base + j;
        v[j] = (idx < N) ? g_deg[idx] : 0;
        s += v[j];
    }
    sh[t] = s;
    __syncthreads();
    // Hillis-Steele inclusive scan over 256 thread sums
    for (int off = 1; off < 256; off <<= 1) {
        int tmp = (t >= off) ? sh[t - off] : 0;
        __syncthreads();
        sh[t] += tmp;
        __syncthreads();
    }
    int excl = g_bsum[b] + sh[t] - s;
#pragma unroll
    for (int j = 0; j < 4; j++) {
        int idx = base + j;
        if (idx < N) {
            g_off[idx] = excl;
            g_cur[idx] = excl;
        }
        excl += v[j];
    }
}

__global__ void fill_kernel(const int* __restrict__ dst, int E, int half, int V) {
    int e = blockIdx.x * blockDim.x + threadIdx.x;
    if (e >= E) return;
    int node = (e < half ? 0 : V) + __ldg(&dst[e]);
    int pos = atomicAdd(&g_cur[node], 1);
    g_eid[pos] = e;
}

// ---------------------------------------------------------------------------
// Gather: one warp per (node,dir). Y[node] = sum over edges of n*x[src]*rel[et].
// No atomics; every row written exactly once (replaces the Y memset too).
// ---------------------------------------------------------------------------
__global__ void gather_kernel(const float* __restrict__ x,
                              const float* __restrict__ rel,
                              const float* __restrict__ enorm,
                              const int* __restrict__ src,
                              const int* __restrict__ et,
                              int N) {
    int gw = (blockIdx.x * blockDim.x + threadIdx.x) >> 5;
    if (gw >= N) return;
    int lane = threadIdx.x & 31;

    int start = __ldg(&g_off[gw]);
    int end   = __ldg(&g_off[gw + 1]);

    float4 acc = make_float4(0.f, 0.f, 0.f, 0.f);

    for (int base = start; base < end; base += 32) {
        int j = base + lane;
        int s = 0, t = 0;
        float n = 0.f;
        if (j < end) {
            int e = __ldg(&g_eid[j]);
            s = __ldg(&src[e]);
            t = __ldg(&et[e]);
            n = __ldg(&enorm[e]);
        }
        int cnt = min(32, end - base);
        for (int q = 0; q < cnt; q++) {
            int   ss = __shfl_sync(0xFFFFFFFFu, s, q);
            int   tt = __shfl_sync(0xFFFFFFFFu, t, q);
            float nn = __shfl_sync(0xFFFFFFFFu, n, q);
            float4 xv = __ldg(reinterpret_cast<const float4*>(x)   + (size_t)ss * 32 + lane);
            float4 rv = __ldg(reinterpret_cast<const float4*>(rel) + (size_t)tt * 32 + lane);
            acc.x += nn * xv.x * rv.x;
            acc.y += nn * xv.y * rv.y;
            acc.z += nn * xv.z * rv.z;
            acc.w += nn * xv.w * rv.w;
        }
    }
    *reinterpret_cast<float4*>(g_Y + (size_t)gw * DD + lane * 4) = acc;
}

// ---------------------------------------------------------------------------
// GEMM: mma.sync fp16 hi/lo, 2 passes, K-chunks of 64 (6 iterations).
// ---------------------------------------------------------------------------
#define ROWB 144
#define OAH 0
#define OAL 18432
#define OBH 36864
#define SMEM_GEMM 55296

__global__ void __launch_bounds__(256, 2) gemm_mma(
    const float* __restrict__ x,
    const float* __restrict__ bias,
    float* __restrict__ hout,
    int V) {

    extern __shared__ __align__(16) unsigned char sm[];
    const uint32_t sb = smem_u32(sm);
    const uint32_t uAh = sb + OAH;
    const uint32_t uAl = sb + OAL;
    const uint32_t uBh = sb + OBH;

    const int tid  = threadIdx.x;
    const int wid  = tid >> 5;
    const int lane = tid & 31;
    const int wm   = wid & 3;
    const int wn   = wid >> 2;
    const int m0   = blockIdx.x * 128;

    float acc[2][8][4];
#pragma unroll
    for (int i = 0; i < 2; i++)
#pragma unroll
        for (int j = 0; j < 8; j++)
#pragma unroll
            for (int k = 0; k < 4; k++) acc[i][j][k] = 0.f;

    for (int c = 0; c < 6; c++) {
        __syncthreads();
        {
            const unsigned char* gh = g_Bh + c * 16384;
#pragma unroll
            for (int j = 0; j < 4; j++) {
                int i = tid + j * 256;
                int r = i >> 3, g = i & 7;
                CP_ASYNC16(uBh + r * ROWB + g * 16, gh + r * 128 + g * 16);
            }
            CP_COMMIT();
        }
        {
            const int k0 = (c & 1) * 64;
            const float* Ab = (c < 2) ? g_Y : (c < 4 ? g_Y + (size_t)V * DD : x);
#pragma unroll
            for (int j = 0; j < 8; j++) {
                int i = tid + j * 256;
                int r = i >> 4, g = i & 15;
                int v = m0 + r;
                float4 z = make_float4(0.f, 0.f, 0.f, 0.f);
                if (v < V)
                    z = *reinterpret_cast<const float4*>(Ab + (size_t)v * DD + k0 + g * 4);
                uint2 hi, lo;
                split4h(z, hi, lo);
                *reinterpret_cast<uint2*>(sm + OAH + r * ROWB + g * 8) = hi;
                *reinterpret_cast<uint2*>(sm + OAL + r * ROWB + g * 8) = lo;
            }
        }
        CP_WAIT0();
        __syncthreads();

#pragma unroll
        for (int k16 = 0; k16 < 4; k16++) {
            const uint32_t kb = k16 * 32 + ((lane >> 4) << 4);
            const uint32_t arow = (uint32_t)(wm * 32 + (lane & 15)) * ROWB + kb;
            const uint32_t brow = (uint32_t)(wn * 64 + (lane & 15)) * ROWB + kb;

            uint32_t ah[2][4], al[2][4], bb[4][4];
#pragma unroll
            for (int mt = 0; mt < 2; mt++) LDSM4(ah[mt], uAh + arow + mt * 16 * ROWB);
#pragma unroll
            for (int nb = 0; nb < 4; nb++) LDSM4(bb[nb], uBh + brow + nb * 16 * ROWB);
#pragma unroll
            for (int mt = 0; mt < 2; mt++)
#pragma unroll
                for (int nb = 0; nb < 4; nb++) {
                    MMA16816F16(acc[mt][nb * 2 + 0], ah[mt], bb[nb][0], bb[nb][2]);
                    MMA16816F16(acc[mt][nb * 2 + 1], ah[mt], bb[nb][1], bb[nb][3]);
                }
#pragma unroll
            for (int mt = 0; mt < 2; mt++) LDSM4(al[mt], uAl + arow + mt * 16 * ROWB);
#pragma unroll
            for (int mt = 0; mt < 2; mt++)
#pragma unroll
                for (int nb = 0; nb < 4; nb++) {
                    MMA16816F16(acc[mt][nb * 2 + 0], al[mt], bb[nb][0], bb[nb][2]);
                    MMA16816F16(acc[mt][nb * 2 + 1], al[mt], bb[nb][1], bb[nb][3]);
                }
        }
    }

    // ---- epilogue: /3 + bias, store h, accumulate BN stats ----
    const float third = 1.f / 3.f;
    float ssum[16], ssq[16];
#pragma unroll
    for (int i = 0; i < 16; i++) { ssum[i] = 0.f; ssq[i] = 0.f; }

#pragma unroll
    for (int mt = 0; mt < 2; mt++) {
        int rowa = m0 + wm * 32 + mt * 16 + (lane >> 2);
        int rowb = rowa + 8;
#pragma unroll
        for (int nt = 0; nt < 8; nt++) {
            int col = wn * 64 + nt * 8 + (lane & 3) * 2;
            float2 bv = *reinterpret_cast<const float2*>(bias + col);
            float h0 = acc[mt][nt][0] * third + bv.x;
            float h1 = acc[mt][nt][1] * third + bv.y;
            float h2 = acc[mt][nt][2] * third + bv.x;
            float h3 = acc[mt][nt][3] * third + bv.y;
            if (rowa < V) {
                *reinterpret_cast<float2*>(hout + (size_t)rowa * DD + col) =
                    make_float2(h0, h1);
                ssum[nt * 2 + 0] += h0; ssq[nt * 2 + 0] += h0 * h0;
                ssum[nt * 2 + 1] += h1; ssq[nt * 2 + 1] += h1 * h1;
            }
            if (rowb < V) {
                *reinterpret_cast<float2*>(hout + (size_t)rowb * DD + col) =
                    make_float2(h2, h3);
                ssum[nt * 2 + 0] += h2; ssq[nt * 2 + 0] += h2 * h2;
                ssum[nt * 2 + 1] += h3; ssq[nt * 2 + 1] += h3 * h3;
            }
        }
    }
#pragma unroll
    for (int i = 0; i < 16; i++) {
#pragma unroll
        for (int off = 4; off <= 16; off <<= 1) {
            ssum[i] += __shfl_xor_sync(0xFFFFFFFFu, ssum[i], off);
            ssq[i]  += __shfl_xor_sync(0xFFFFFFFFu, ssq[i],  off);
        }
    }
    __syncthreads();
    float* Ssum = reinterpret_cast<float*>(sm);
    float* Ssq  = reinterpret_cast<float*>(sm + 4096);
#pragma unroll
    for (int j = 0; j < 4; j++) { Ssum[tid + j * 256] = 0.f; Ssq[tid + j * 256] = 0.f; }
    __syncthreads();
    if (lane < 4) {
#pragma unroll
        for (int nt = 0; nt < 8; nt++) {
            int col = wn * 64 + nt * 8 + lane * 2;
            Ssum[wid * 128 + col]     = ssum[nt * 2 + 0];
            Ssum[wid * 128 + col + 1] = ssum[nt * 2 + 1];
            Ssq [wid * 128 + col]     = ssq[nt * 2 + 0];
            Ssq [wid * 128 + col + 1] = ssq[nt * 2 + 1];
        }
    }
    __syncthreads();
    if (tid < 128) {
        float a = 0.f, b = 0.f;
#pragma unroll
        for (int w = 0; w < 8; w++) { a += Ssum[w * 128 + tid]; b += Ssq[w * 128 + tid]; }
        atomicAdd(&g_stats[tid],       a);
        atomicAdd(&g_stats[128 + tid], b);
    }
}

// ---------------------------------------------------------------------------
// BatchNorm + ReLU, in place on h
// ---------------------------------------------------------------------------
__global__ void bn_kernel(float* __restrict__ h, int V) {
    __shared__ float ms[128];
    __shared__ float rs[128];
    if (threadIdx.x < 128) {
        float invn = 1.f / (float)V;
        float s  = g_stats[threadIdx.x];
        float sq = g_stats[128 + threadIdx.x];
        float m  = s * invn;
        float var = sq * invn - m * m;
        ms[threadIdx.x] = m;
        rs[threadIdx.x] = rsqrtf(var + 1e-5f);
    }
    __syncthreads();
    size_t total = (size_t)V * 32;
    float4* h4 = reinterpret_cast<float4*>(h);
    for (size_t i = (size_t)blockIdx.x * blockDim.x + threadIdx.x; i < total;
         i += (size_t)gridDim.x * blockDim.x) {
        int c4 = (int)(i & 31) * 4;
        float4 hv = h4[i];
        hv.x = fmaxf((hv.x - ms[c4 + 0]) * rs[c4 + 0], 0.f);
        hv.y = fmaxf((hv.y - ms[c4 + 1]) * rs[c4 + 1], 0.f);
        hv.z = fmaxf((hv.z - ms[c4 + 2]) * rs[c4 + 2], 0.f);
        hv.w = fmaxf((hv.w - ms[c4 + 3]) * rs[c4 + 3], 0.f);
        h4[i] = hv;
    }
}

// ---------------------------------------------------------------------------
// rel_repr @ w_rel, 4 rel rows per block
// ---------------------------------------------------------------------------
__global__ void relw_kernel(const float* __restrict__ rel,
                            const float* __restrict__ w_rel,
                            float* __restrict__ out, int R) {
    __shared__ float rr[4][128];
    int r0 = blockIdx.x * 4;
    int c = threadIdx.x;
#pragma unroll
    for (int j = 0; j < 4; j++)
        rr[j][c] = (r0 + j < R) ? rel[(size_t)(r0 + j) * DD + c] : 0.f;
    __syncthreads();
    float a0 = 0.f, a1 = 0.f, a2 = 0.f, a3 = 0.f;
#pragma unroll 4
    for (int k = 0; k < 128; k++) {
        float w = __ldg(&w_rel[(size_t)k * DD + c]);
        a0 += rr[0][k] * w;
        a1 += rr[1][k] * w;
        a2 += rr[2][k] * w;
        a3 += rr[3][k] * w;
    }
    if (r0 + 0 < R) out[(size_t)(r0 + 0) * DD + c] = a0;
    if (r0 + 1 < R) out[(size_t)(r0 + 1) * DD + c] = a1;
    if (r0 + 2 < R) out[(size_t)(r0 + 2) * DD + c] = a2;
    if (r0 + 3 < R) out[(size_t)(r0 + 3) * DD + c] = a3;
}

// ---------------------------------------------------------------------------
extern "C" void kernel_launch(void* const* d_in, const int* in_sizes, int n_in,
                              void* d_out, int out_size) {
    const float* x        = (const float*)d_in[0];
    const float* rel      = (const float*)d_in[1];
    const float* enorm    = (const float*)d_in[2];
    const float* in_w     = (const float*)d_in[3];
    const float* out_w    = (const float*)d_in[4];
    const float* loop_w   = (const float*)d_in[5];
    const float* w_rel    = (const float*)d_in[6];
    const float* loop_rel = (const float*)d_in[7];
    const float* bias     = (const float*)d_in[8];
    const int*   src      = (const int*)d_in[9];
    const int*   dst      = (const int*)d_in[10];
    const int*   et       = (const int*)d_in[11];

    int V = in_sizes[0] / DD;
    int R = in_sizes[1] / DD;
    int E = in_sizes[2];
    int half = E / 2;
    int N = 2 * V;
    int NB = (N + 1023) / 1024;

    float* h    = (float*)d_out;
    float* out2 = h + (size_t)V * DD;

    void* dptr = nullptr; void* sptr = nullptr;
    cudaGetSymbolAddress(&dptr, g_deg);
    cudaGetSymbolAddress(&sptr, g_stats);
    cudaMemsetAsync(dptr, 0, (size_t)N * sizeof(int), 0);
    cudaMemsetAsync(sptr, 0, 2 * DD * sizeof(float), 0);

    cudaFuncSetAttribute(gemm_mma, cudaFuncAttributeMaxDynamicSharedMemorySize,
                         SMEM_GEMM);

    prep_w<<<6, 256>>>(in_w, out_w, loop_w, loop_rel);
    hist_kernel<<<(E + 255) / 256, 256>>>(dst, E, half, V);
    scan1_kernel<<<NB, 256>>>(N);
    scan2_kernel<<<1, 32>>>(NB, N);
    scan3_kernel<<<NB, 256>>>(N);
    fill_kernel<<<(E + 255) / 256, 256>>>(dst, E, half, V);
    gather_kernel<<<(N + 7) / 8, 256>>>(x, rel, enorm, src, et, N);
    gemm_mma<<<(V + 127) / 128, 256, SMEM_GEMM>>>(x, bias, h, V);
    bn_kernel<<<1024, 256>>>(h, V);
    relw_kernel<<<(R + 3) / 4, 128>>>(rel, w_rel, out2, R);
}